// round 1
// baseline (speedup 1.0000x reference)
#include <cuda_runtime.h>

// RITS-I recurrent imputation: B=256 independent sequences, T=2048 sequential
// LSTM steps. One CTA per batch element; gate weights cached in registers;
// inputs double-buffered in registers; small weights in padded shared memory.

#define NB   256
#define NT   2048
#define NI   64
#define NH   32
#define NG   128   // 4*NH
#define NC   2
#define TPB  128

__device__ __forceinline__ float sigmoid_f(float x) {
    return 1.0f / (1.0f + __expf(-x));
}

__device__ __forceinline__ float tanh_f(float x) {
    float ax = fabsf(x);
    float e  = __expf(-2.0f * ax);           // in (0, 1], never overflows
    float r  = (1.0f - e) / (1.0f + e);
    return copysignf(r, x);
}

__global__ void __launch_bounds__(TPB)
rits_kernel(const float* __restrict__ values,
            const float* __restrict__ masks,
            const float* __restrict__ deltas,
            const float* __restrict__ W_decay, const float* __restrict__ b_decay,
            const float* __restrict__ W_reg,   const float* __restrict__ b_reg,
            const float* __restrict__ W_ih,    const float* __restrict__ b_ih,
            const float* __restrict__ W_hh,    const float* __restrict__ b_hh,
            const float* __restrict__ W_out,   const float* __restrict__ b_out,
            float* __restrict__ out)
{
    // Padded rows so 8-lane LDS.128 phases hit distinct banks.
    __shared__ __align__(16) float Wd_s[NH][68];   // W_decay rows padded 64->68
    __shared__ __align__(16) float Wr_s[NI][36];   // W_reg   rows padded 32->36
    __shared__ __align__(16) float bd_s[NH];
    __shared__ __align__(16) float br_s[NI];
    __shared__ __align__(16) float d_s[NI];
    __shared__ __align__(16) float inp_s[2 * NI];  // [ x_c | m ]
    __shared__ __align__(16) float h_s[NH];
    __shared__ __align__(16) float gates_s[NG];

    const int tid = threadIdx.x;
    const int b   = blockIdx.x;

    // ---- stage small weights into shared ----
    for (int idx = tid; idx < NH * NI; idx += TPB)
        Wd_s[idx / NI][idx % NI] = W_decay[idx];
    for (int idx = tid; idx < NI * NH; idx += TPB)
        Wr_s[idx / NH][idx % NH] = W_reg[idx];
    if (tid < NH) { bd_s[tid] = b_decay[tid]; h_s[tid] = 0.0f; }
    if (tid < NI) { br_s[tid] = b_reg[tid]; }

    // ---- gate weights: thread k owns gate row k in registers ----
    float4 wih[2 * NI / 4];   // 32 float4 = W_ih[k][0..127]
    float4 whh[NH / 4];       // 8  float4 = W_hh[k][0..31]
    {
        const float4* p = reinterpret_cast<const float4*>(W_ih + (size_t)tid * (2 * NI));
        #pragma unroll
        for (int q = 0; q < 2 * NI / 4; q++) wih[q] = p[q];
        const float4* ph = reinterpret_cast<const float4*>(W_hh + (size_t)tid * NH);
        #pragma unroll
        for (int q = 0; q < NH / 4; q++) whh[q] = ph[q];
    }
    const float bsum = b_ih[tid] + b_hh[tid];

    float c_reg = 0.0f;       // thread j < NH owns cell state c[j]

    // ---- input prefetch registers (thread i < NI owns feature i) ----
    const size_t base = (size_t)b * NT * NI;
    float cx = 0.0f, cm = 0.0f, cd = 0.0f;
    if (tid < NI) {
        cx = values[base + tid];
        cm = masks [base + tid];
        cd = deltas[base + tid];
    }

    float* __restrict__ imp_out = out + (size_t)NB * NC;  // y_h first, then imputations

    const int j4 = tid >> 2;   // gamma output index (0..31)
    const int p4 = tid & 3;    // quarter of the 64-wide dot

    __syncthreads();

    for (int t = 0; t < NT; t++) {
        // -- stage current m, d into shared; keep x, m in regs for phase B --
        const float xr = cx, mr = cm;
        if (tid < NI) { d_s[tid] = cd; inp_s[NI + tid] = cm; }
        __syncthreads();

        // -- prefetch next step's inputs (latency hidden by this step) --
        if (tid < NI && t + 1 < NT) {
            const size_t o = base + (size_t)(t + 1) * NI + tid;
            cx = values[o]; cm = masks[o]; cd = deltas[o];
        }

        // -- Phase A: gamma = exp(-relu(W_decay d + b)); h *= gamma --
        {
            float s = 0.0f;
            const float4* wrow = reinterpret_cast<const float4*>(&Wd_s[j4][p4 * 16]);
            const float4* drow = reinterpret_cast<const float4*>(&d_s[p4 * 16]);
            #pragma unroll
            for (int q = 0; q < 4; q++) {
                float4 w = wrow[q], v = drow[q];
                s += w.x * v.x + w.y * v.y + w.z * v.z + w.w * v.w;
            }
            s += __shfl_xor_sync(0xffffffffu, s, 1);
            s += __shfl_xor_sync(0xffffffffu, s, 2);
            if (p4 == 0) {
                const float a = s + bd_s[j4];
                h_s[j4] *= __expf(-fmaxf(a, 0.0f));
            }
        }
        __syncthreads();

        // -- Phase B: x_h = W_reg h + b; x_c = m*x + (1-m)*x_h --
        if (tid < NI) {
            float s = br_s[tid];
            const float4* wrow = reinterpret_cast<const float4*>(&Wr_s[tid][0]);
            const float4* hp   = reinterpret_cast<const float4*>(h_s);
            #pragma unroll
            for (int q = 0; q < NH / 4; q++) {
                float4 w = wrow[q], v = hp[q];
                s += w.x * v.x + w.y * v.y + w.z * v.z + w.w * v.w;
            }
            const float xc = mr * xr + (1.0f - mr) * s;
            inp_s[tid] = xc;
            imp_out[base + (size_t)t * NI + tid] = xc;
        }
        __syncthreads();

        // -- Phase C: gates[k] = W_ih[k].[x_c|m] + W_hh[k].h + biases --
        {
            float a0 = bsum, a1 = 0.0f;
            const float4* ip = reinterpret_cast<const float4*>(inp_s);
            #pragma unroll
            for (int q = 0; q < 2 * NI / 4; q += 2) {
                float4 v0 = ip[q];
                float4 v1 = ip[q + 1];
                a0 += wih[q].x     * v0.x + wih[q].y     * v0.y
                    + wih[q].z     * v0.z + wih[q].w     * v0.w;
                a1 += wih[q + 1].x * v1.x + wih[q + 1].y * v1.y
                    + wih[q + 1].z * v1.z + wih[q + 1].w * v1.w;
            }
            const float4* hp = reinterpret_cast<const float4*>(h_s);
            #pragma unroll
            for (int q = 0; q < NH / 4; q++) {
                float4 v = hp[q];
                a0 += whh[q].x * v.x + whh[q].y * v.y
                    + whh[q].z * v.z + whh[q].w * v.w;
            }
            gates_s[tid] = a0 + a1;
        }
        __syncthreads();

        // -- Phase D: LSTM state update (thread j < NH owns lane j) --
        if (tid < NH) {
            const float ig = sigmoid_f(gates_s[tid]);
            const float fg = sigmoid_f(gates_s[NH + tid]);
            const float gg = tanh_f   (gates_s[2 * NH + tid]);
            const float og = sigmoid_f(gates_s[3 * NH + tid]);
            const float cn = fg * c_reg + ig * gg;
            c_reg = cn;
            h_s[tid] = og * tanh_f(cn);
        }
        __syncthreads();
    }

    // -- output head: y = W_out h + b_out --
    if (tid < NC) {
        float s = b_out[tid];
        #pragma unroll
        for (int q = 0; q < NH; q++) s += W_out[tid * NH + q] * h_s[q];
        out[b * NC + tid] = s;
    }
}

extern "C" void kernel_launch(void* const* d_in, const int* in_sizes, int n_in,
                              void* d_out, int out_size)
{
    (void)in_sizes; (void)n_in; (void)out_size;
    const float* values  = (const float*)d_in[0];
    const float* masks   = (const float*)d_in[1];
    const float* deltas  = (const float*)d_in[2];
    const float* W_decay = (const float*)d_in[3];
    const float* b_decay = (const float*)d_in[4];
    const float* W_reg   = (const float*)d_in[5];
    const float* b_reg   = (const float*)d_in[6];
    const float* W_ih    = (const float*)d_in[7];
    const float* b_ih    = (const float*)d_in[8];
    const float* W_hh    = (const float*)d_in[9];
    const float* b_hh    = (const float*)d_in[10];
    const float* W_out   = (const float*)d_in[11];
    const float* b_out   = (const float*)d_in[12];
    float* out = (float*)d_out;

    rits_kernel<<<NB, TPB>>>(values, masks, deltas,
                             W_decay, b_decay, W_reg, b_reg,
                             W_ih, b_ih, W_hh, b_hh,
                             W_out, b_out, out);
}

// round 2
// speedup vs baseline: 1.3187x; 1.3187x over previous
#include <cuda_runtime.h>

// RITS-I recurrent imputation. One CTA (128 threads) per batch element.
// Per step, work is rebalanced into 3 FFMA segments with 4 barriers:
//   seg1: decay dot (A) + m-half of gate dot   (m known at step start)
//   seg2: W_hh*h (all threads) + x_c/imputation (threads < 64)
//   seg3: x_c-half of gate dot
//   D:    LSTM pointwise (threads < 32) + next-step input staging (< 64)

#define NB   256
#define NT   2048
#define NI   64
#define NH   32
#define NG   128   // 4*NH
#define NC   2
#define TPB  128

__device__ __forceinline__ float sigmoid_f(float x) {
    float e = __expf(-x);
    return __fdividef(1.0f, 1.0f + e);          // MUFU.EX2 + MUFU.RCP
}

__device__ __forceinline__ float tanh_f(float x) {
    float ax = fabsf(x);
    float e  = __expf(-2.0f * ax);              // in (0,1], never overflows
    float r  = __fdividef(1.0f - e, 1.0f + e);
    return copysignf(r, x);
}

__device__ __forceinline__ float dot4(float4 w, float4 v) {
    return w.x * v.x + w.y * v.y + w.z * v.z + w.w * v.w;
}

__global__ void __launch_bounds__(TPB, 2)
rits_kernel(const float* __restrict__ values,
            const float* __restrict__ masks,
            const float* __restrict__ deltas,
            const float* __restrict__ W_decay, const float* __restrict__ b_decay,
            const float* __restrict__ W_reg,   const float* __restrict__ b_reg,
            const float* __restrict__ W_ih,    const float* __restrict__ b_ih,
            const float* __restrict__ W_hh,    const float* __restrict__ b_hh,
            const float* __restrict__ W_out,   const float* __restrict__ b_out,
            float* __restrict__ out)
{
    __shared__ __align__(16) float Wd_s[NH][68];   // rows padded 64->68 (bank-safe)
    __shared__ __align__(16) float Wr_s[NI][36];   // rows padded 32->36
    __shared__ __align__(16) float bd_s[NH];
    __shared__ __align__(16) float br_s[NI];
    __shared__ __align__(16) float d_s[NI];
    __shared__ __align__(16) float m_s[NI];
    __shared__ __align__(16) float xc_s[NI];
    __shared__ __align__(16) float h_s[NH];
    __shared__ __align__(16) float gates_s[NG];

    const int tid = threadIdx.x;
    const int b   = blockIdx.x;

    // ---- stage small weights into shared ----
    for (int idx = tid; idx < NH * NI; idx += TPB)
        Wd_s[idx / NI][idx % NI] = W_decay[idx];
    for (int idx = tid; idx < NI * NH; idx += TPB)
        Wr_s[idx / NH][idx % NH] = W_reg[idx];
    if (tid < NH) { bd_s[tid] = b_decay[tid]; h_s[tid] = 0.0f; }
    if (tid < NI) { br_s[tid] = b_reg[tid]; }

    // ---- gate row tid cached in registers, split x-half / m-half ----
    float4 wihx[NI / 4];      // W_ih[tid][ 0.. 63]
    float4 wihm[NI / 4];      // W_ih[tid][64..127]
    float4 whh [NH / 4];      // W_hh[tid][ 0.. 31]
    {
        const float4* p = reinterpret_cast<const float4*>(W_ih + (size_t)tid * (2 * NI));
        #pragma unroll
        for (int q = 0; q < NI / 4; q++) wihx[q] = p[q];
        #pragma unroll
        for (int q = 0; q < NI / 4; q++) wihm[q] = p[NI / 4 + q];
        const float4* ph = reinterpret_cast<const float4*>(W_hh + (size_t)tid * NH);
        #pragma unroll
        for (int q = 0; q < NH / 4; q++) whh[q] = ph[q];
    }
    const float bsum = b_ih[tid] + b_hh[tid];

    float c_reg = 0.0f;                       // thread j < NH owns c[j]

    const size_t base = (size_t)b * NT * NI;
    float cx = 0.0f, cm = 0.0f, cd = 0.0f;    // prefetch regs (thread i < NI: feature i)
    if (tid < NI) {
        cx = values[base + tid];
        cm = masks [base + tid];
        cd = deltas[base + tid];
        d_s[tid] = cd;                        // stage step 0
        m_s[tid] = cm;
    }

    float* __restrict__ imp_out = out + (size_t)NB * NC;

    const int j4 = tid >> 2;                  // decay output index (0..31)
    const int p4 = tid & 3;                   // quarter of the 64-wide dot

    __syncthreads();

    for (int t = 0; t < NT; t++) {
        // ================= seg1: decay dot + m-half of gates =================
        const float xr = cx, mr = cm;         // snapshot step-t inputs
        if (tid < NI && t + 1 < NT) {         // prefetch step t+1 (latency hidden)
            const size_t o = base + (size_t)(t + 1) * NI + tid;
            cx = values[o]; cm = masks[o]; cd = deltas[o];
        }

        // decay quarter-dot
        float s = 0.0f;
        {
            const float4* wrow = reinterpret_cast<const float4*>(&Wd_s[j4][p4 * 16]);
            const float4* drow = reinterpret_cast<const float4*>(&d_s[p4 * 16]);
            #pragma unroll
            for (int q = 0; q < 4; q++) s += dot4(wrow[q], drow[q]);
        }
        s += __shfl_xor_sync(0xffffffffu, s, 1);
        s += __shfl_xor_sync(0xffffffffu, s, 2);   // latency hidden by m-half below

        // m-half of gate row (independent of h)
        float g0 = bsum, g1 = 0.0f;
        {
            const float4* mp = reinterpret_cast<const float4*>(m_s);
            #pragma unroll
            for (int q = 0; q < NI / 4; q += 2) {
                g0 += dot4(wihm[q],     mp[q]);
                g1 += dot4(wihm[q + 1], mp[q + 1]);
            }
        }

        if (p4 == 0) {
            const float a = s + bd_s[j4];
            h_s[j4] *= __expf(-fmaxf(a, 0.0f));    // h *= gamma
        }
        __syncthreads();                           // bar1: decayed h visible

        // ================= seg2: W_hh*h (all) + x_c (threads < NI) ===========
        float g2 = 0.0f, g3 = 0.0f;
        {
            const float4* hp = reinterpret_cast<const float4*>(h_s);
            #pragma unroll
            for (int q = 0; q < NH / 4; q += 2) {
                g2 += dot4(whh[q],     hp[q]);
                g3 += dot4(whh[q + 1], hp[q + 1]);
            }
        }
        if (tid < NI) {
            float s0 = br_s[tid], s1 = 0.0f;
            const float4* wrow = reinterpret_cast<const float4*>(&Wr_s[tid][0]);
            const float4* hp   = reinterpret_cast<const float4*>(h_s);
            #pragma unroll
            for (int q = 0; q < NH / 4; q += 2) {
                s0 += dot4(wrow[q],     hp[q]);
                s1 += dot4(wrow[q + 1], hp[q + 1]);
            }
            const float xc = mr * xr + (1.0f - mr) * (s0 + s1);
            xc_s[tid] = xc;
            imp_out[base + (size_t)t * NI + tid] = xc;
        }
        __syncthreads();                           // bar2: x_c visible

        // ================= seg3: x_c-half of gates ===========================
        {
            const float4* xp = reinterpret_cast<const float4*>(xc_s);
            #pragma unroll
            for (int q = 0; q < NI / 4; q += 2) {
                g0 += dot4(wihx[q],     xp[q]);
                g1 += dot4(wihx[q + 1], xp[q + 1]);
            }
        }
        gates_s[tid] = (g0 + g2) + (g1 + g3);
        __syncthreads();                           // bar3: gates visible

        // ================= D: LSTM update + next-step staging ================
        if (tid < NH) {
            const float ig = sigmoid_f(gates_s[tid]);
            const float fg = sigmoid_f(gates_s[NH + tid]);
            const float gg = tanh_f   (gates_s[2 * NH + tid]);
            const float og = sigmoid_f(gates_s[3 * NH + tid]);
            const float cn = fg * c_reg + ig * gg;
            c_reg = cn;
            h_s[tid] = og * tanh_f(cn);
        }
        if (tid < NI) {                            // stage step t+1 inputs
            d_s[tid] = cd;
            m_s[tid] = cm;
        }
        __syncthreads();                           // bar4: h, d_s, m_s ready
    }

    // ---- output head: y = W_out h + b_out ----
    if (tid < NC) {
        float s = b_out[tid];
        #pragma unroll
        for (int q = 0; q < NH; q++) s += W_out[tid * NH + q] * h_s[q];
        out[b * NC + tid] = s;
    }
}

extern "C" void kernel_launch(void* const* d_in, const int* in_sizes, int n_in,
                              void* d_out, int out_size)
{
    (void)in_sizes; (void)n_in; (void)out_size;
    const float* values  = (const float*)d_in[0];
    const float* masks   = (const float*)d_in[1];
    const float* deltas  = (const float*)d_in[2];
    const float* W_decay = (const float*)d_in[3];
    const float* b_decay = (const float*)d_in[4];
    const float* W_reg   = (const float*)d_in[5];
    const float* b_reg   = (const float*)d_in[6];
    const float* W_ih    = (const float*)d_in[7];
    const float* b_ih    = (const float*)d_in[8];
    const float* W_hh    = (const float*)d_in[9];
    const float* b_hh    = (const float*)d_in[10];
    const float* W_out   = (const float*)d_in[11];
    const float* b_out   = (const float*)d_in[12];
    float* out = (float*)d_out;

    rits_kernel<<<NB, TPB>>>(values, masks, deltas,
                             W_decay, b_decay, W_reg, b_reg,
                             W_ih, b_ih, W_hh, b_hh,
                             W_out, b_out, out);
}

// round 3
// speedup vs baseline: 1.3230x; 1.0032x over previous
#include <cuda_runtime.h>

// RITS-I recurrent imputation, GB300 sm_103a.
// 2 batch elements fused per CTA via packed f32x2 math (fma.rn.f32x2).
// grid = 128 CTAs (one per SM, single wave), 256 threads:
//   "low"  threads 0..127 : gate row k  — m-half of W_ih + W_hh (weights in regs)
//   "hi"   threads 128..255: gate row hk — x-half of W_ih; also W_reg (x_h) and
//                            W_decay (gamma) quarter-dots; LSTM pointwise tail.
// 3 __syncthreads per step. h_s is stored pre-decayed (h_new * gamma_{t+1}).

#define NB  256
#define NT  2048
#define NI  64
#define NH  32
#define NC  2
#define TPB 256

typedef unsigned long long ull;

__device__ __forceinline__ ull pack2(float x, float y) {
    ull r; asm("mov.b64 %0, {%1, %2};" : "=l"(r) : "f"(x), "f"(y)); return r;
}
__device__ __forceinline__ void unpack2(ull v, float& x, float& y) {
    asm("mov.b64 {%0, %1}, %2;" : "=f"(x), "=f"(y) : "l"(v));
}
__device__ __forceinline__ ull ffma2(ull a, ull b, ull c) {
    ull d; asm("fma.rn.f32x2 %0, %1, %2, %3;" : "=l"(d) : "l"(a), "l"(b), "l"(c));
    return d;
}
__device__ __forceinline__ ull fadd2(ull a, ull b) {
    ull d; asm("add.rn.f32x2 %0, %1, %2;" : "=l"(d) : "l"(a), "l"(b)); return d;
}

__device__ __forceinline__ float sigmoid_f(float x) {
    float e = __expf(-x);
    return __fdividef(1.0f, 1.0f + e);
}
__device__ __forceinline__ float tanh_f(float x) {
    float ax = fabsf(x);
    float e  = __expf(-2.0f * ax);
    float r  = __fdividef(1.0f - e, 1.0f + e);
    return copysignf(r, x);
}

__global__ void __launch_bounds__(TPB, 1)
rits_kernel(const float* __restrict__ values,
            const float* __restrict__ masks,
            const float* __restrict__ deltas,
            const float* __restrict__ W_decay, const float* __restrict__ b_decay,
            const float* __restrict__ W_reg,   const float* __restrict__ b_reg,
            const float* __restrict__ W_ih,    const float* __restrict__ b_ih,
            const float* __restrict__ W_hh,    const float* __restrict__ b_hh,
            const float* __restrict__ W_out,   const float* __restrict__ b_out,
            float* __restrict__ out)
{
    // Interleaved packed layout: feature f -> floats [2f] (batch0), [2f+1] (batch1)
    __shared__ __align__(16) float m_sf [2 * NI];
    __shared__ __align__(16) float d_sf [2 * NI];
    __shared__ __align__(16) float x_sf [2 * NI];
    __shared__ __align__(16) float xc_sf[2 * NI];
    __shared__ __align__(16) float h_sf [2 * NH];
    __shared__ __align__(16) float2 gpA[4 * NH];   // partial gates (m-half + Whh*h)
    __shared__ __align__(16) float2 gpB[4 * NH];   // partial gates (x-half)

    const int tid = threadIdx.x;
    const bool low = (tid < 128);
    const int  k   = tid;          // low: gate row
    const int  hk  = tid - 128;    // hi index
    const int  hj  = hk >> 1;      // hi: x_h feature
    const int  hf  = hk & 1;       // hi: half of the 32-wide W_reg dot
    const int  j4  = hk >> 2;      // hi: gamma output row
    const int  p4  = hk & 3;       // hi: quarter of the 64-wide decay dot

    const size_t base0 = (size_t)(2 * blockIdx.x)     * NT * NI;
    const size_t base1 = (size_t)(2 * blockIdx.x + 1) * NT * NI;

    // ---- unified weight register file: both roles share the same 96 ull ----
    ull W[96];
    {
        const float* s1 = low ? (W_ih + (size_t)k * (2 * NI) + NI)   // m-half
                              : (W_ih + (size_t)hk * (2 * NI));      // x-half
        #pragma unroll
        for (int i = 0; i < 64; i++) W[i] = pack2(s1[i], s1[i]);
        const float* s2 = low ? (W_hh + (size_t)k * NH)
                              : (W_reg + (size_t)hj * NH + hf * 16);
        #pragma unroll
        for (int i = 0; i < 16; i++) W[64 + i] = pack2(s2[i], s2[i]);
        const float* s3 = low ? (W_hh + (size_t)k * NH + 16)
                              : (W_decay + (size_t)j4 * NI + p4 * 16);
        #pragma unroll
        for (int i = 0; i < 16; i++) W[80 + i] = pack2(s3[i], s3[i]);
    }
    const float bsum = low ? (b_ih[k] + b_hh[k]) : 0.0f;
    const ull   br2  = low ? 0ull : pack2(b_reg[hj], b_reg[hj]);
    const float bd   = low ? 0.0f : b_decay[j4];

    float c_reg = 0.0f;                     // hi p4 in {0,2}: cell state (its batch)

    // ---- stage step 0, prefetch step 1 (low threads: one scalar each) ----
    float px = 0.f, pm = 0.f, pd = 0.f;
    size_t bb = 0;
    if (low) {
        const int sj = k >> 1;
        bb = (k & 1) ? base1 : base0;
        x_sf[k] = values[bb + sj];
        m_sf[k] = masks [bb + sj];
        d_sf[k] = deltas[bb + sj];
        px = values[bb + NI + sj];
        pm = masks [bb + NI + sj];
        pd = deltas[bb + NI + sj];
    }
    if (tid < 2 * NH) h_sf[tid] = 0.0f;
    __syncthreads();

    // ---- gmh for t=0: m-half dot + biases (kept in registers) ----
    ull gm0 = 0ull, gm1 = 0ull;
    if (low) {
        gm0 = pack2(bsum, bsum);
        const ulonglong2* mp = reinterpret_cast<const ulonglong2*>(m_sf);
        #pragma unroll
        for (int q = 0; q < 32; q++) {
            ulonglong2 v = mp[q];
            gm0 = ffma2(W[2 * q],     v.x, gm0);
            gm1 = ffma2(W[2 * q + 1], v.y, gm1);
        }
    }
    __syncthreads();

    float* __restrict__ imp_out = out + (size_t)NB * NC;

    for (int t = 0; t < NT; t++) {
        // ========== Phase A ==========
        if (low) {
            // gate partial: gmh + Whh . h   (h_sf is already decayed)
            ull a0 = gm0, a1 = gm1;
            const ulonglong2* hp = reinterpret_cast<const ulonglong2*>(h_sf);
            #pragma unroll
            for (int q = 0; q < 16; q++) {
                ulonglong2 v = hp[q];
                a0 = ffma2(W[64 + 2 * q], v.x, a0);
                a1 = ffma2(W[65 + 2 * q], v.y, a1);
            }
            ull g = fadd2(a0, a1);
            float gx, gy; unpack2(g, gx, gy);
            gpA[k] = make_float2(gx, gy);
        } else {
            // x_h = W_reg . h (split across thread pairs) ; x_c ; imputation
            ull a0 = 0ull, a1 = 0ull;
            const ulonglong2* hp = reinterpret_cast<const ulonglong2*>(h_sf + hf * 32);
            #pragma unroll
            for (int q = 0; q < 8; q++) {
                ulonglong2 v = hp[q];
                a0 = ffma2(W[64 + 2 * q], v.x, a0);
                a1 = ffma2(W[65 + 2 * q], v.y, a1);
            }
            ull xh = fadd2(a0, a1);
            xh = fadd2(xh, __shfl_xor_sync(0xffffffffu, xh, 1));
            if (hf == 0) {
                float xh0, xh1; unpack2(fadd2(xh, br2), xh0, xh1);
                const float m0 = m_sf[2 * hj], m1 = m_sf[2 * hj + 1];
                const float x0 = x_sf[2 * hj], x1 = x_sf[2 * hj + 1];
                const float xc0 = m0 * x0 + (1.0f - m0) * xh0;
                const float xc1 = m1 * x1 + (1.0f - m1) * xh1;
                xc_sf[2 * hj]     = xc0;
                xc_sf[2 * hj + 1] = xc1;
                imp_out[base0 + (size_t)t * NI + hj] = xc0;
                imp_out[base1 + (size_t)t * NI + hj] = xc1;
            }
        }
        __syncthreads();

        // ========== Phase B ==========
        if (!low) {
            // x-half of gate row hk
            ull a0 = 0ull, a1 = 0ull;
            const ulonglong2* xp = reinterpret_cast<const ulonglong2*>(xc_sf);
            #pragma unroll
            for (int q = 0; q < 32; q++) {
                ulonglong2 v = xp[q];
                a0 = ffma2(W[2 * q],     v.x, a0);
                a1 = ffma2(W[2 * q + 1], v.y, a1);
            }
            ull g = fadd2(a0, a1);
            float gx, gy; unpack2(g, gx, gy);
            gpB[hk] = make_float2(gx, gy);
        } else {
            // stage step t+1, prefetch step t+2
            x_sf[k] = px; m_sf[k] = pm; d_sf[k] = pd;
            if (t + 2 < NT) {
                const size_t o = bb + (size_t)(t + 2) * NI + (k >> 1);
                px = values[o]; pm = masks[o]; pd = deltas[o];
            }
        }
        __syncthreads();

        // ========== Phase C ==========
        if (low) {
            // m-half gate partial for step t+1 (m_sf holds t+1 now)
            gm0 = pack2(bsum, bsum); gm1 = 0ull;
            const ulonglong2* mp = reinterpret_cast<const ulonglong2*>(m_sf);
            #pragma unroll
            for (int q = 0; q < 32; q++) {
                ulonglong2 v = mp[q];
                gm0 = ffma2(W[2 * q],     v.x, gm0);
                gm1 = ffma2(W[2 * q + 1], v.y, gm1);
            }
        } else {
            // gamma_{t+1} quarter-dot (d_sf holds t+1)
            ull a0 = 0ull, a1 = 0ull;
            const ulonglong2* dp = reinterpret_cast<const ulonglong2*>(d_sf + p4 * 32);
            #pragma unroll
            for (int q = 0; q < 8; q++) {
                ulonglong2 v = dp[q];
                a0 = ffma2(W[80 + 2 * q], v.x, a0);
                a1 = ffma2(W[81 + 2 * q], v.y, a1);
            }
            ull g = fadd2(a0, a1);
            g = fadd2(g, __shfl_xor_sync(0xffffffffu, g, 1));
            g = fadd2(g, __shfl_xor_sync(0xffffffffu, g, 2));

            if ((p4 & 1) == 0) {
                // p4==0 handles batch 0, p4==2 handles batch 1 of row j4
                const int q2 = p4 >> 1;
                float gsx, gsy; unpack2(g, gsx, gsy);
                const float gsum  = q2 ? gsy : gsx;
                const float gamma = (t + 1 < NT)
                                  ? __expf(-fmaxf(gsum + bd, 0.0f)) : 1.0f;
                const float* gA = reinterpret_cast<const float*>(gpA);
                const float* gB = reinterpret_cast<const float*>(gpB);
                const float gi = gA[2 * j4 + q2]              + gB[2 * j4 + q2];
                const float gf = gA[2 * (NH + j4) + q2]       + gB[2 * (NH + j4) + q2];
                const float gg = gA[2 * (2 * NH + j4) + q2]   + gB[2 * (2 * NH + j4) + q2];
                const float go = gA[2 * (3 * NH + j4) + q2]   + gB[2 * (3 * NH + j4) + q2];
                const float ig = sigmoid_f(gi);
                const float fg = sigmoid_f(gf);
                const float gG = tanh_f(gg);
                const float og = sigmoid_f(go);
                const float cn = fg * c_reg + ig * gG;
                c_reg = cn;
                h_sf[2 * j4 + q2] = og * tanh_f(cn) * gamma;  // pre-decayed
            }
        }
        __syncthreads();
    }

    // ---- output head: y = W_out h + b_out (4 scalars: 2 batches x 2 classes) ----
    if (tid < 4) {
        const int cc = tid & 1, q = tid >> 1;
        float s = b_out[cc];
        #pragma unroll
        for (int jj = 0; jj < NH; jj++) s += W_out[cc * NH + jj] * h_sf[2 * jj + q];
        out[(size_t)(2 * blockIdx.x + q) * NC + cc] = s;
    }
}

extern "C" void kernel_launch(void* const* d_in, const int* in_sizes, int n_in,
                              void* d_out, int out_size)
{
    (void)in_sizes; (void)n_in; (void)out_size;
    const float* values  = (const float*)d_in[0];
    const float* masks   = (const float*)d_in[1];
    const float* deltas  = (const float*)d_in[2];
    const float* W_decay = (const float*)d_in[3];
    const float* b_decay = (const float*)d_in[4];
    const float* W_reg   = (const float*)d_in[5];
    const float* b_reg   = (const float*)d_in[6];
    const float* W_ih    = (const float*)d_in[7];
    const float* b_ih    = (const float*)d_in[8];
    const float* W_hh    = (const float*)d_in[9];
    const float* b_hh    = (const float*)d_in[10];
    const float* W_out   = (const float*)d_in[11];
    const float* b_out   = (const float*)d_in[12];
    float* out = (float*)d_out;

    rits_kernel<<<NB / 2, TPB>>>(values, masks, deltas,
                                 W_decay, b_decay, W_reg, b_reg,
                                 W_ih, b_ih, W_hh, b_hh,
                                 W_out, b_out, out);
}